// round 8
// baseline (speedup 1.0000x reference)
#include <cuda_runtime.h>

// Problem shape (fixed by reference setup_inputs)
#define BB 32
#define NN 8
#define LQ 256
#define LD 512
#define DD 768
#define D4 (DD / 4)                      // 192 float4 per feature row
#define LSPLIT 8                          // question L-dim split
#define LCH (LQ / LSPLIT)                 // 32 q-rows per q-block
#define QBLK (BB * LSPLIT)                // 256 question blocks
#define RC 16                             // doc rows per work chunk
#define CPS (LD / RC)                     // 32 chunks per (b,n) slice
#define NCHUNK (BB * NN * CPS)            // 8192 doc chunks
#define NWORK 1184                        // persistent doc workers (~8/SM)
#define TT D4                             // 192 threads: one float4 column each
#define F4_PER_SLICE (LD * D4)            // 98304 float4 per (b,n)

// Scratch (allocation-free rule: __device__ globals; zero-initialized at load)
__device__ float4       g_qpart[QBLK * D4];
__device__ double       g_acc;
__device__ unsigned int g_count;   // worker completion counter
__device__ unsigned int g_qcount;  // question-block completion counter
__device__ unsigned int g_work;    // dynamic chunk queue head

// ---------------------------------------------------------------------------
// Single fused kernel.
//  blocks [0, QBLK):  question partial sums -> g_qpart, bump g_qcount, exit.
//  blocks [QBLK, +NWORK): persistent workers; grab 16-row doc chunks off
//  g_work, column-sum each (weight-free stream), dot with qsum (after a
//  one-time wait for g_qcount), accumulate in double, one atomic at end.
//  Last finishing worker writes out and resets scratch (graph-replay safe).
__global__ void __launch_bounds__(TT) fused(const float4* __restrict__ q,
                                            const float*  __restrict__ docs,
                                            const int*    __restrict__ is_ans,
                                            float*        __restrict__ out) {
    const int t = threadIdx.x;            // 0..191 = float4 column

    // ---------------- question blocks (exit early) ----------------
    if (blockIdx.x < QBLK) {
        const int b = blockIdx.x / LSPLIT;
        const int c = blockIdx.x % LSPLIT;
        const float4* base = q + ((size_t)b * LQ + (size_t)c * LCH) * D4 + t;
        float4 s = make_float4(0.f, 0.f, 0.f, 0.f);
#pragma unroll 8
        for (int l = 0; l < LCH; ++l) {
            const float4 v = base[(size_t)l * D4];
            s.x += v.x; s.y += v.y; s.z += v.z; s.w += v.w;
        }
        g_qpart[(size_t)blockIdx.x * D4 + t] = s;
        __threadfence();
        __syncthreads();
        if (t == 0) atomicAdd(&g_qcount, 1u);
        return;
    }

    // ---------------- persistent doc workers ----------------
    __shared__ unsigned int s_chunk;
    __shared__ double       warp_sums[TT / 32];

    double accd = 0.0;
    bool   qdone = false;

    for (;;) {
        if (t == 0) s_chunk = atomicAdd(&g_work, 1u);
        __syncthreads();
        const unsigned int i = s_chunk;
        __syncthreads();
        if (i >= NCHUNK) break;

        const int slice = i / CPS;        // 0..255 (= b*NN + n)
        const int part  = i % CPS;
        const int b     = slice / NN;

        const float4* base = (const float4*)docs +
                             (size_t)slice * F4_PER_SLICE +
                             (size_t)part * RC * D4 + t;

        // Column sum over RC rows: pure streaming (evict-first loads).
        float4 cs = make_float4(0.f, 0.f, 0.f, 0.f);
#pragma unroll
        for (int l = 0; l < RC; ++l) {
            const float4 v = __ldcs(base + (size_t)l * D4);
            cs.x += v.x; cs.y += v.y; cs.z += v.z; cs.w += v.w;
        }

        // One-time wait for question partials (already done in steady state).
        if (!qdone) {
            if (t == 0) {
                while (atomicAdd(&g_qcount, 0u) < QBLK) { }
            }
            __syncthreads();
            __threadfence();
            qdone = true;
        }

        // Gather this column's q-weight (sum of the 8 partials) and dot.
        float4 w = make_float4(0.f, 0.f, 0.f, 0.f);
#pragma unroll
        for (int c = 0; c < LSPLIT; ++c) {
            const float4 v = g_qpart[(size_t)(b * LSPLIT + c) * D4 + t];
            w.x += v.x; w.y += v.y; w.z += v.z; w.w += v.w;
        }
        float r = cs.x * w.x + cs.y * w.y + cs.z * w.z + cs.w * w.w;
        accd += (is_ans[slice] != 0) ? -(double)r : (double)r;
    }

    // Warp reduce in double, then cross-warp.
#pragma unroll
    for (int off = 16; off > 0; off >>= 1)
        accd += __shfl_down_sync(0xFFFFFFFFu, accd, off);

    const int warp = t >> 5;
    if ((t & 31) == 0) warp_sums[warp] = accd;
    __syncthreads();

    if (t == 0) {
        double s = 0.0;
#pragma unroll
        for (int w2 = 0; w2 < TT / 32; ++w2) s += warp_sums[w2];
        atomicAdd(&g_acc, s);
        __threadfence();
        const unsigned int done = atomicAdd(&g_count, 1u);
        if (done == NWORK - 1) {
            const double tot = *((volatile double*)&g_acc);
            out[0] = (float)(tot * (1.0 / ((double)LQ * (double)LD)));
            // Reset scratch for the next graph replay.
            g_acc    = 0.0;
            g_qcount = 0u;
            g_work   = 0u;
            __threadfence();
            g_count  = 0u;
        }
    }
}

// ---------------------------------------------------------------------------
extern "C" void kernel_launch(void* const* d_in, const int* in_sizes, int n_in,
                              void* d_out, int out_size) {
    const float* questions = (const float*)d_in[0];
    const float* docs      = (const float*)d_in[1];
    const int*   is_ans    = (const int*)d_in[2];
    float*       out       = (float*)d_out;

    fused<<<QBLK + NWORK, TT>>>((const float4*)questions, docs, is_ans, out);
}

// round 9
// speedup vs baseline: 1.0836x; 1.0836x over previous
#include <cuda_runtime.h>

// Problem shape (fixed by reference setup_inputs)
#define BB 32
#define NN 8
#define LQ 256
#define LD 512
#define DD 768
#define D4 (DD / 4)                      // 192 float4 per feature row
#define LSPLIT 8                          // question L-dim split
#define LCH (LQ / LSPLIT)                 // 32 q-rows per q-block
#define QBLK (BB * LSPLIT)                // 256 question blocks
#define BPS 4                             // doc blocks per (b,n) slice
#define NBLK2 (BB * NN * BPS)             // 1024 doc blocks
#define TT D4                             // 192 threads: one float4 column each
#define ROWS (LD / BPS)                   // 128 doc rows per doc block
#define HROWS (ROWS / 2)                  // 64 rows per stream (dual-stream MLP)
#define F4_PER_SLICE (LD * D4)            // 98304 float4 per (b,n)

// Scratch (allocation-free rule: __device__ globals; zero-initialized at load)
__device__ float4       g_qpart[QBLK * D4];
__device__ double       g_acc;
__device__ unsigned int g_count;   // doc-block completion counter
__device__ unsigned int g_qcount;  // question-block completion counter

// ---------------------------------------------------------------------------
// Single fused kernel (static work split — R7 layout, dual-stream inner loop).
//  blocks [0, QBLK):       question partial sums -> g_qpart, bump g_qcount.
//  blocks [QBLK, +NBLK2):  stream a 128-row doc chunk as TWO independent
//                          64-row streams (doubles per-thread MLP), then dot
//                          with qsum, reduce, atomic into g_acc.
//  Last doc block writes out and resets scratch (graph-replay safe).
__global__ void __launch_bounds__(TT, 8) fused(const float4* __restrict__ q,
                                               const float*  __restrict__ docs,
                                               const int*    __restrict__ is_ans,
                                               float*        __restrict__ out) {
    const int t = threadIdx.x;            // 0..191 = float4 column

    // ---------------- question blocks (exit early) ----------------
    if (blockIdx.x < QBLK) {
        const int b = blockIdx.x / LSPLIT;
        const int c = blockIdx.x % LSPLIT;
        const float4* base = q + ((size_t)b * LQ + (size_t)c * LCH) * D4 + t;
        float4 s = make_float4(0.f, 0.f, 0.f, 0.f);
#pragma unroll 8
        for (int l = 0; l < LCH; ++l) {
            const float4 v = base[(size_t)l * D4];
            s.x += v.x; s.y += v.y; s.z += v.z; s.w += v.w;
        }
        g_qpart[(size_t)blockIdx.x * D4 + t] = s;
        __threadfence();
        __syncthreads();
        if (t == 0) atomicAdd(&g_qcount, 1u);
        return;
    }

    // ---------------- doc blocks ----------------
    __shared__ double warp_sums[TT / 32];

    const int db    = blockIdx.x - QBLK;  // 0..1023
    const int slice = db / BPS;           // 0..255  (= b*NN + n)
    const int part  = db % BPS;
    const int b     = slice / NN;

    const float4* p0 = (const float4*)docs +
                       (size_t)slice * F4_PER_SLICE +
                       (size_t)part * ROWS * D4 + t;
    const float4* p1 = p0 + (size_t)HROWS * D4;

    // Two independent 64-row streams -> ~8 LDG.128 in flight per thread.
    float4 cs0 = make_float4(0.f, 0.f, 0.f, 0.f);
    float4 cs1 = make_float4(0.f, 0.f, 0.f, 0.f);
#pragma unroll 4
    for (int l = 0; l < HROWS; ++l) {
        const float4 a = __ldcs(p0 + (size_t)l * D4);
        const float4 c = __ldcs(p1 + (size_t)l * D4);
        cs0.x += a.x; cs0.y += a.y; cs0.z += a.z; cs0.w += a.w;
        cs1.x += c.x; cs1.y += c.y; cs1.z += c.z; cs1.w += c.w;
    }
    float4 cs = make_float4(cs0.x + cs1.x, cs0.y + cs1.y,
                            cs0.z + cs1.z, cs0.w + cs1.w);

    // Wait for question partials (normally already complete — no real spin).
    if (t == 0) {
        while (atomicAdd(&g_qcount, 0u) < QBLK) { }
    }
    __syncthreads();
    __threadfence();  // acquire: make g_qpart writes visible to all threads

    // Gather this column's q-weight (sum of the 8 partials) and dot.
    float4 w = make_float4(0.f, 0.f, 0.f, 0.f);
#pragma unroll
    for (int c = 0; c < LSPLIT; ++c) {
        const float4 v = g_qpart[(size_t)(b * LSPLIT + c) * D4 + t];
        w.x += v.x; w.y += v.y; w.z += v.z; w.w += v.w;
    }
    float acc = cs.x * w.x + cs.y * w.y + cs.z * w.z + cs.w * w.w;
    acc *= (is_ans[slice] != 0) ? -1.f : 1.f;

    // Warp reduce (fp32), then cross-warp in double.
#pragma unroll
    for (int off = 16; off > 0; off >>= 1)
        acc += __shfl_down_sync(0xFFFFFFFFu, acc, off);

    const int warp = t >> 5;
    if ((t & 31) == 0) warp_sums[warp] = (double)acc;
    __syncthreads();

    if (t == 0) {
        double s = 0.0;
#pragma unroll
        for (int w2 = 0; w2 < TT / 32; ++w2) s += warp_sums[w2];
        atomicAdd(&g_acc, s);
        __threadfence();
        const unsigned int done = atomicAdd(&g_count, 1u);
        if (done == NBLK2 - 1) {
            const double tot = *((volatile double*)&g_acc);
            out[0] = (float)(tot * (1.0 / ((double)LQ * (double)LD)));
            // Reset scratch for the next graph replay.
            g_acc    = 0.0;
            g_qcount = 0u;
            __threadfence();
            g_count  = 0u;
        }
    }
}

// ---------------------------------------------------------------------------
extern "C" void kernel_launch(void* const* d_in, const int* in_sizes, int n_in,
                              void* d_out, int out_size) {
    const float* questions = (const float*)d_in[0];
    const float* docs      = (const float*)d_in[1];
    const int*   is_ans    = (const int*)d_in[2];
    float*       out       = (float*)d_out;

    fused<<<QBLK + NBLK2, TT>>>((const float4*)questions, docs, is_ans, out);
}

// round 10
// speedup vs baseline: 1.1495x; 1.0608x over previous
#include <cuda_runtime.h>

// Problem shape (fixed by reference setup_inputs)
#define BB 32
#define NN 8
#define LQ 256
#define LD 512
#define DD 768
#define D4 (DD / 4)                      // 192 float4 per feature row
#define LSPLIT 4                          // question L-dim split
#define LCH (LQ / LSPLIT)                 // 64 q-rows per q-block
#define QBLK (BB * LSPLIT)                // 128 question blocks
#define BPS 4                             // doc blocks per (b,n) slice
#define NBLK2 (BB * NN * BPS)             // 1024 doc blocks
#define TT D4                             // 192 threads: one float4 column each
#define ROWS (LD / BPS)                   // 128 doc rows per doc block
#define F4_PER_SLICE (LD * D4)            // 98304 float4 per (b,n)
// Total grid = 128 + 1024 = 1152 <= 1184 (8 CTAs/SM at 32 regs) -> ONE wave.

// Scratch (allocation-free rule: __device__ globals; zero-initialized at load)
__device__ float4       g_qpart[QBLK * D4];
__device__ double       g_acc;
__device__ unsigned int g_count;   // doc-block completion counter
__device__ unsigned int g_qcount;  // question-block completion counter

// ---------------------------------------------------------------------------
// Single fused kernel, single wave.
//  blocks [0, QBLK):       question partial sums -> g_qpart, bump g_qcount.
//  blocks [QBLK, +NBLK2):  stream a 128-row doc chunk (column sums, weight-
//                          free), wait for q partials (already done), dot
//                          with qsum, reduce, atomic into g_acc.
//  Last doc block writes out and resets scratch (graph-replay safe).
__global__ void __launch_bounds__(TT) fused(const float4* __restrict__ q,
                                            const float*  __restrict__ docs,
                                            const int*    __restrict__ is_ans,
                                            float*        __restrict__ out) {
    const int t = threadIdx.x;            // 0..191 = float4 column

    // ---------------- question blocks (exit early) ----------------
    if (blockIdx.x < QBLK) {
        const int b = blockIdx.x / LSPLIT;
        const int c = blockIdx.x % LSPLIT;
        const float4* base = q + ((size_t)b * LQ + (size_t)c * LCH) * D4 + t;
        float4 s = make_float4(0.f, 0.f, 0.f, 0.f);
#pragma unroll 8
        for (int l = 0; l < LCH; ++l) {
            const float4 v = base[(size_t)l * D4];
            s.x += v.x; s.y += v.y; s.z += v.z; s.w += v.w;
        }
        g_qpart[(size_t)blockIdx.x * D4 + t] = s;
        __threadfence();
        __syncthreads();
        if (t == 0) atomicAdd(&g_qcount, 1u);
        return;
    }

    // ---------------- doc blocks ----------------
    __shared__ double warp_sums[TT / 32];

    const int db    = blockIdx.x - QBLK;  // 0..1023
    const int slice = db / BPS;           // 0..255  (= b*NN + n)
    const int part  = db % BPS;
    const int b     = slice / NN;

    const float4* base = (const float4*)docs +
                         (size_t)slice * F4_PER_SLICE +
                         (size_t)part * ROWS * D4 + t;

    // Column sum over ROWS rows: pure streaming (evict-first loads).
    float4 cs = make_float4(0.f, 0.f, 0.f, 0.f);
#pragma unroll 8
    for (int l = 0; l < ROWS; ++l) {
        const float4 v = __ldcs(base + (size_t)l * D4);
        cs.x += v.x; cs.y += v.y; cs.z += v.z; cs.w += v.w;
    }

    // Wait for question partials (normally already complete — no real spin).
    if (t == 0) {
        while (atomicAdd(&g_qcount, 0u) < QBLK) { }
    }
    __syncthreads();
    __threadfence();  // acquire: make g_qpart writes visible to all threads

    // Gather this column's q-weight (sum of the 4 partials) and dot.
    float4 w = make_float4(0.f, 0.f, 0.f, 0.f);
#pragma unroll
    for (int c = 0; c < LSPLIT; ++c) {
        const float4 v = g_qpart[(size_t)(b * LSPLIT + c) * D4 + t];
        w.x += v.x; w.y += v.y; w.z += v.z; w.w += v.w;
    }
    float acc = cs.x * w.x + cs.y * w.y + cs.z * w.z + cs.w * w.w;
    acc *= (is_ans[slice] != 0) ? -1.f : 1.f;

    // Warp reduce (fp32), then cross-warp in double.
#pragma unroll
    for (int off = 16; off > 0; off >>= 1)
        acc += __shfl_down_sync(0xFFFFFFFFu, acc, off);

    const int warp = t >> 5;
    if ((t & 31) == 0) warp_sums[warp] = (double)acc;
    __syncthreads();

    if (t == 0) {
        double s = 0.0;
#pragma unroll
        for (int w2 = 0; w2 < TT / 32; ++w2) s += warp_sums[w2];
        atomicAdd(&g_acc, s);
        __threadfence();
        const unsigned int done = atomicAdd(&g_count, 1u);
        if (done == NBLK2 - 1) {
            const double tot = *((volatile double*)&g_acc);
            out[0] = (float)(tot * (1.0 / ((double)LQ * (double)LD)));
            // Reset scratch for the next graph replay.
            g_acc    = 0.0;
            g_qcount = 0u;
            __threadfence();
            g_count  = 0u;
        }
    }
}

// ---------------------------------------------------------------------------
extern "C" void kernel_launch(void* const* d_in, const int* in_sizes, int n_in,
                              void* d_out, int out_size) {
    const float* questions = (const float*)d_in[0];
    const float* docs      = (const float*)d_in[1];
    const int*   is_ans    = (const int*)d_in[2];
    float*       out       = (float*)d_out;

    fused<<<QBLK + NBLK2, TT>>>((const float4*)questions, docs, is_ans, out);
}